// round 17
// baseline (speedup 1.0000x reference)
#include <cuda_runtime.h>
#include <cuda_fp16.h>
#include <math.h>
#include <stdint.h>

#define NB 32
#define NC 256
#define NH 64
#define NW 64
#define NHW 4096
#define NCHW (NC*NHW)
#define EPSV 1e-5f

// Scratch (allocation-free rule: __device__ globals)
__device__ float  g_pooled[NB*NC];
__device__ int    g_idx[NB];
__device__ __half g_x16[(size_t)NB*NCHW];     // fp16 copy of x (written by pool)
__device__ __half g_feat16[(size_t)NB*NCHW];  // fp16 feature scratch, natural [c][n]
__device__ __half g_wt16[4][NC*NC];           // fp16 weights: e0_pw,e1_pw,e2_pw,e2_k

__device__ __forceinline__ float gelu_exact(float z) {
    return 0.5f * z * (1.0f + erff(z * 0.7071067811865475f));
}
__device__ __forceinline__ uint32_t smem_addr_u32(const void* p) {
    return (uint32_t)__cvta_generic_to_shared(p);
}
__device__ __forceinline__ void cp_async16(uint32_t dst, const void* src) {
    asm volatile("cp.async.ca.shared.global [%0], [%1], 16;" :: "r"(dst), "l"(src));
}
#define CP_COMMIT() asm volatile("cp.async.commit_group;")
#define CP_WAIT(n)  asm volatile("cp.async.wait_group %0;" :: "n"(n))

__device__ __forceinline__ uint32_t h2u(__half2 h) {
    return *reinterpret_cast<uint32_t*>(&h);
}

// ---------------------------------------------------------------------------
// 1) Fused: global average pool (+ fp16 copy of x) + weight pre-convert
// ---------------------------------------------------------------------------
__global__ void pool_prep_kernel(const float* __restrict__ x,
                                 const float* __restrict__ w0, const float* __restrict__ w1,
                                 const float* __restrict__ w2, const float* __restrict__ k2) {
    if (blockIdx.x < NB*NC) {
        int bc = blockIdx.x;
        const float4* p = reinterpret_cast<const float4*>(x + (size_t)bc * NHW);
        uint2* o16 = reinterpret_cast<uint2*>(g_x16 + (size_t)bc * NHW);
        float s = 0.f;
        for (int i = threadIdx.x; i < NHW/4; i += 256) {
            float4 v = p[i];
            s += (v.x + v.y) + (v.z + v.w);
            o16[i] = make_uint2(h2u(__floats2half2_rn(v.x, v.y)),
                                h2u(__floats2half2_rn(v.z, v.w)));
        }
        __shared__ float red[8];
        #pragma unroll
        for (int o = 16; o > 0; o >>= 1) s += __shfl_down_sync(0xffffffffu, s, o);
        if ((threadIdx.x & 31) == 0) red[threadIdx.x >> 5] = s;
        __syncthreads();
        if (threadIdx.x < 8) {
            float t = red[threadIdx.x];
            #pragma unroll
            for (int o = 4; o > 0; o >>= 1) t += __shfl_down_sync(0xffu, t, o);
            if (threadIdx.x == 0) g_pooled[bc] = t * (1.0f / NHW);
        }
    } else {
        int i = (blockIdx.x - NB*NC) * 256 + threadIdx.x;
        int m = i >> 16;
        int o = i & 0xFFFF;
        const float* src = (m == 0) ? w0 : (m == 1) ? w1 : (m == 2) ? w2 : k2;
        g_wt16[m][o] = __float2half_rn(src[o]);
    }
}

// ---------------------------------------------------------------------------
// 2) Router
// ---------------------------------------------------------------------------
__global__ void route_kernel(const float* __restrict__ rw, const float* __restrict__ rb) {
    int b = threadIdx.x;
    if (b >= NB) return;
    float best = -1e30f; int bi = 0;
    #pragma unroll
    for (int j = 0; j < 3; j++) {
        float s = rb[j];
        const float* w = rw + j*NC;
        const float* p = g_pooled + b*NC;
        for (int c = 0; c < NC; c++) s = fmaf(p[c], w[c], s);
        if (s > best) { best = s; bi = j; }
    }
    g_idx[b] = bi;
}

// ---------------------------------------------------------------------------
// 3a) Depthwise 3x3 conv + BN + exact GELU (R9-proven); output fp16 natural
// ---------------------------------------------------------------------------
#define SMC 70

template<int D>
__device__ __forceinline__ void dwconv_plane(
    float (*sm)[SMC], const float* __restrict__ xp, const float* __restrict__ kw9,
    float scale, float mm, float bb, __half* __restrict__ outp)
{
    const int tid = threadIdx.x;

    for (int i = tid; i < 272; i += 256) {
        int r = i / 68, c = i % 68;
        sm[(r < 2) ? r : r + 64][c] = 0.f;
    }
    {
        int r = 2 + (tid >> 2);
        int c = tid & 3;
        sm[r][(c < 2) ? c : c + 64] = 0.f;
    }

    #pragma unroll
    for (int i = 0; i < 4; i++) {
        int idx = tid + i*256;
        int y = idx >> 4, x4 = (idx & 15) * 4;
        float4 v = reinterpret_cast<const float4*>(xp)[idx];
        sm[y+2][x4+2+0] = v.x;
        sm[y+2][x4+2+1] = v.y;
        sm[y+2][x4+2+2] = v.z;
        sm[y+2][x4+2+3] = v.w;
    }
    __syncthreads();

    const int y  = tid >> 2;
    const int x0 = (tid & 3) * 16;

    float acc[16];
    #pragma unroll
    for (int j = 0; j < 16; j++) acc[j] = 0.f;

    #pragma unroll
    for (int dy = 0; dy < 3; dy++) {
        const float* row = &sm[y + 2 + (dy-1)*D][x0 + 2 - D];
        const float w0 = kw9[dy*3 + 0];
        const float w1 = kw9[dy*3 + 1];
        const float w2 = kw9[dy*3 + 2];
        float v[16 + 2*D];
        #pragma unroll
        for (int j = 0; j < 16 + 2*D; j++) v[j] = row[j];
        #pragma unroll
        for (int j = 0; j < 16; j++)
            acc[j] = fmaf(w0, v[j], fmaf(w1, v[j+D], fmaf(w2, v[j+2*D], acc[j])));
    }

    uint32_t pk[8];
    #pragma unroll
    for (int jj = 0; jj < 8; jj++) {
        float z0 = (acc[2*jj]   - mm) * scale + bb;
        float z1 = (acc[2*jj+1] - mm) * scale + bb;
        pk[jj] = h2u(__floats2half2_rn(gelu_exact(z0), gelu_exact(z1)));
    }
    __half* op = outp + y*NW + x0;
    *reinterpret_cast<uint4*>(op)     = make_uint4(pk[0], pk[1], pk[2], pk[3]);
    *reinterpret_cast<uint4*>(op + 8) = make_uint4(pk[4], pk[5], pk[6], pk[7]);
}

__global__ void __launch_bounds__(256) dwconv_bn_gelu_kernel(
    int boff,
    const float* __restrict__ x,
    const float* __restrict__ k0, const float* __restrict__ g0, const float* __restrict__ b0,
    const float* __restrict__ m0, const float* __restrict__ v0,
    const float* __restrict__ k1, const float* __restrict__ g1, const float* __restrict__ b1,
    const float* __restrict__ m1, const float* __restrict__ v1)
{
    __shared__ float sm[68][SMC];
    const int b = blockIdx.y + boff;
    const int e = g_idx[b];
    if (e == 2) return;
    const int c = blockIdx.x;

    const float gg = (e == 0 ? g0[c] : g1[c]);
    const float vv = (e == 0 ? v0[c] : v1[c]);
    const float mm = (e == 0 ? m0[c] : m1[c]);
    const float bb = (e == 0 ? b0[c] : b1[c]);
    const float scale = gg * rsqrtf(vv + EPSV);
    const float* kw = (e == 0 ? k0 : k1) + c * 9;
    const float* xp = x + ((size_t)b*NC + c) * NHW;
    __half* outp = g_feat16 + ((size_t)b*NC + c) * NHW;

    if (e == 0) dwconv_plane<1>(sm, xp, kw, scale, mm, bb, outp);
    else        dwconv_plane<2>(sm, xp, kw, scale, mm, bb, outp);
}

// ---------------------------------------------------------------------------
// fp16 tensor-core primitives
// ---------------------------------------------------------------------------
__device__ __forceinline__ void ldsm4(uint32_t r[4], uint32_t a) {
    asm volatile("ldmatrix.sync.aligned.m8n8.x4.shared.b16 {%0,%1,%2,%3}, [%4];"
        : "=r"(r[0]), "=r"(r[1]), "=r"(r[2]), "=r"(r[3]) : "r"(a));
}
__device__ __forceinline__ void ldsm4t(uint32_t r[4], uint32_t a) {
    asm volatile("ldmatrix.sync.aligned.m8n8.x4.trans.shared.b16 {%0,%1,%2,%3}, [%4];"
        : "=r"(r[0]), "=r"(r[1]), "=r"(r[2]), "=r"(r[3]) : "r"(a));
}
__device__ __forceinline__ void mma16816(float c[4], const uint32_t a[4],
                                         uint32_t b0, uint32_t b1) {
    asm volatile(
        "mma.sync.aligned.m16n8k16.row.col.f32.f16.f16.f32 "
        "{%0,%1,%2,%3}, {%4,%5,%6,%7}, {%8,%9}, {%0,%1,%2,%3};"
        : "+f"(c[0]), "+f"(c[1]), "+f"(c[2]), "+f"(c[3])
        : "r"(a[0]), "r"(a[1]), "r"(a[2]), "r"(a[3]), "r"(b0), "r"(b1));
}

#define A_CHUNK 10240
#define B_STAGE 8704

// ---------------------------------------------------------------------------
// fp16 pipelined GEMM core (R14-proven)
// ---------------------------------------------------------------------------
__device__ __forceinline__ void hgemm_pipe(
    char* AsPtr, char* BsPtr,
    const __half* __restrict__ A, const __half* __restrict__ Bm,
    int m0, int n0, float acc[2][8][4])
{
    const int tid  = threadIdx.x;
    const int lane = tid & 31;
    const int wid  = tid >> 5;
    const int wm   = wid & 3;
    const int wn   = wid >> 2;
    const int grp  = lane >> 3;
    const int lr   = lane & 7;

    const uint32_t asU = smem_addr_u32(AsPtr);
    const uint32_t bsU = smem_addr_u32(BsPtr);

    const int am0 = tid >> 2,        au0 = tid & 3;
    const int am1 = (tid+256) >> 2,  au1 = tid & 3;
    const __half* aSrc0 = A + (size_t)(m0 + am0) * NC + au0*8;
    const __half* aSrc1 = A + (size_t)(m0 + am1) * NC + au1*8;
    char* aDst0 = AsPtr + am0*80 + au0*16;
    char* aDst1 = AsPtr + am1*80 + au1*16;

    const int bk = tid >> 4, bu = tid & 15;
    const __half* bSrc0 = Bm + (size_t)bk * NHW + n0 + bu*8;
    const uint32_t bD0 = bsU + bk*272 + bu*16;
    const uint32_t bD1 = bsU + (bk+16)*272 + bu*16;

    const uint32_t aFrag = (uint32_t)((wm*32 + (grp&1)*8 + lr)*80 + (grp>>1)*16);
    const uint32_t bFrag = (uint32_t)(((grp&1)*8 + lr)*272 + wn*128 + (grp>>1)*16);

    cp_async16(bD0, bSrc0);
    cp_async16(bD1, bSrc0 + (size_t)16*NHW);
    CP_COMMIT();
    cp_async16(bD0 + B_STAGE, bSrc0 + (size_t)32*NHW);
    cp_async16(bD1 + B_STAGE, bSrc0 + (size_t)48*NHW);
    CP_COMMIT();
    {
        uint4 v0 = *reinterpret_cast<const uint4*>(aSrc0);
        uint4 v1 = *reinterpret_cast<const uint4*>(aSrc1);
        *reinterpret_cast<uint4*>(aDst0) = v0;
        *reinterpret_cast<uint4*>(aDst1) = v1;
    }
    CP_WAIT(1);
    __syncthreads();

    int bufA = 0;
    #pragma unroll 1
    for (int kc = 0; kc < 8; kc++) {
        const uint32_t bsStage = bsU + (uint32_t)(kc % 3) * B_STAGE;

        if (kc + 2 < 8) {
            const uint32_t so = (uint32_t)((kc + 2) % 3) * B_STAGE;
            const __half* s = bSrc0 + (size_t)(kc + 2) * 32 * NHW;
            cp_async16(bD0 + so, s);
            cp_async16(bD1 + so, s + (size_t)16*NHW);
            CP_COMMIT();
        }
        uint4 av0, av1;
        const bool has_next = (kc + 1) < 8;
        if (has_next) {
            av0 = *reinterpret_cast<const uint4*>(aSrc0 + (kc+1)*32);
            av1 = *reinterpret_cast<const uint4*>(aSrc1 + (kc+1)*32);
        }

        const uint32_t asCur = asU + (uint32_t)bufA * A_CHUNK;
        #pragma unroll
        for (int ks = 0; ks < 2; ks++) {
            uint32_t a0[4], a1[4];
            ldsm4(a0, asCur + aFrag + ks*32);
            ldsm4(a1, asCur + aFrag + 1280 + ks*32);
            uint32_t b[4][4];
            #pragma unroll
            for (int j = 0; j < 4; j++)
                ldsm4t(b[j], bsStage + bFrag + ks*4352 + j*32);
            #pragma unroll
            for (int nt = 0; nt < 8; nt++) {
                const uint32_t b0 = b[nt>>1][(nt&1)*2];
                const uint32_t b1 = b[nt>>1][(nt&1)*2 + 1];
                mma16816(acc[0][nt], a0, b0, b1);
                mma16816(acc[1][nt], a1, b0, b1);
            }
        }

        if (has_next) {
            char* base = AsPtr + (bufA ^ 1) * A_CHUNK;
            *reinterpret_cast<uint4*>(base + am0*80 + au0*16) = av0;
            *reinterpret_cast<uint4*>(base + am1*80 + au1*16) = av1;
            bufA ^= 1;
        }

        if (kc + 2 < 8) { CP_WAIT(1); } else { CP_WAIT(0); }
        __syncthreads();
    }
}

// ---------------------------------------------------------------------------
// 3b) feat GEMM: feat[b] = bn_gelu(e2_k @ x16[b]) for idx==2, fp16 out
// ---------------------------------------------------------------------------
__global__ void __launch_bounds__(256, 2) feat_gemm_kernel(
    int boff,
    const float* __restrict__ p0, const float* __restrict__ p1,
    const float* __restrict__ p2, const float* __restrict__ p3)
{
    __shared__ __align__(16) char As[2*A_CHUNK];
    __shared__ __align__(16) char Bs[3*B_STAGE];

    const int bz = blockIdx.z + boff;
    if (g_idx[bz] != 2) return;
    const int m0 = blockIdx.y * 128;
    const int n0 = blockIdx.x * 128;

    float acc[2][8][4];
    #pragma unroll
    for (int i = 0; i < 2; i++)
        #pragma unroll
        for (int j = 0; j < 8; j++)
            #pragma unroll
            for (int t = 0; t < 4; t++) acc[i][j][t] = 0.f;

    hgemm_pipe(As, Bs, g_wt16[3], g_x16 + (size_t)bz*NCHW, m0, n0, acc);

    const int lane = threadIdx.x & 31;
    const int wid  = threadIdx.x >> 5;
    const int wm   = wid & 3;
    const int wn   = wid >> 2;
    const int gID  = lane >> 2;
    const int qid  = lane & 3;
    __half* Cm = g_feat16 + (size_t)bz*NCHW;

    #pragma unroll
    for (int mt = 0; mt < 2; mt++) {
        #pragma unroll
        for (int half = 0; half < 2; half++) {
            const int o = m0 + wm*32 + mt*16 + half*8 + gID;
            float sc = p0[o] * rsqrtf(p3[o] + EPSV);
            float mm = p2[o];
            float bb = p1[o];
            __half* cp = Cm + (size_t)o * NHW + n0 + wn*64 + qid*2;
            #pragma unroll
            for (int nt = 0; nt < 8; nt++) {
                float z0 = acc[mt][nt][half*2 + 0];
                float z1 = acc[mt][nt][half*2 + 1];
                z0 = (z0 - mm) * sc + bb; z0 = gelu_exact(z0);
                z1 = (z1 - mm) * sc + bb; z1 = gelu_exact(z1);
                *reinterpret_cast<__half2*>(cp + nt*8) = __floats2half2_rn(z0, z1);
            }
        }
    }
}

// ---------------------------------------------------------------------------
// 4) out GEMM: out[b] = e{idx}_pw @ feat16[b] + e{idx}_pb (fp32 out)
// ---------------------------------------------------------------------------
__global__ void __launch_bounds__(256, 2) out_gemm_kernel(
    int boff,
    const float* __restrict__ pb0, const float* __restrict__ pb1,
    const float* __restrict__ pb2, float* __restrict__ out)
{
    __shared__ __align__(16) char As[2*A_CHUNK];
    __shared__ __align__(16) char Bs[3*B_STAGE];

    const int bz = blockIdx.z + boff;
    const int e  = g_idx[bz];
    const float* pb = (e == 0) ? pb0 : (e == 1 ? pb1 : pb2);
    const int m0 = blockIdx.y * 128;
    const int n0 = blockIdx.x * 128;

    float acc[2][8][4];
    #pragma unroll
    for (int i = 0; i < 2; i++)
        #pragma unroll
        for (int j = 0; j < 8; j++)
            #pragma unroll
            for (int t = 0; t < 4; t++) acc[i][j][t] = 0.f;

    hgemm_pipe(As, Bs, g_wt16[e], g_feat16 + (size_t)bz*NCHW, m0, n0, acc);

    const int lane = threadIdx.x & 31;
    const int wid  = threadIdx.x >> 5;
    const int wm   = wid & 3;
    const int wn   = wid >> 2;
    const int gID  = lane >> 2;
    const int qid  = lane & 3;
    float* Cm = out + (size_t)bz*NCHW;

    #pragma unroll
    for (int mt = 0; mt < 2; mt++) {
        #pragma unroll
        for (int half = 0; half < 2; half++) {
            const int o = m0 + wm*32 + mt*16 + half*8 + gID;
            const float bb = pb[o];
            float* cp = Cm + (size_t)o * NHW + n0 + wn*64 + qid*2;
            #pragma unroll
            for (int nt = 0; nt < 8; nt++) {
                *reinterpret_cast<float2*>(cp + nt*8) =
                    make_float2(acc[mt][nt][half*2 + 0] + bb,
                                acc[mt][nt][half*2 + 1] + bb);
            }
        }
    }
}

// ---------------------------------------------------------------------------
// Launch: half-batch pipelined fork-join.
//   s0: pool -> route -> dwconv(h0) -> dwconv(h1) -> [wait eF1] out(h1) -> [wait eO0]
//   s1: [wait fork] feat(h0) [eF0] -> feat(h1) [eF1]
//   s2: [wait eD0,eF0] out(h0) [eO0]   (concurrent with dwconv/feat h1)
// Streams/events are host objects created once via static init.
// ---------------------------------------------------------------------------
static cudaStream_t g_str[2];
static cudaEvent_t  g_ev[5];
static bool g_init = [](){
    for (int j = 0; j < 2; j++)
        cudaStreamCreateWithFlags(&g_str[j], cudaStreamNonBlocking);
    for (int j = 0; j < 5; j++)
        cudaEventCreateWithFlags(&g_ev[j], cudaEventDisableTiming);
    return true;
}();

extern "C" void kernel_launch(void* const* d_in, const int* in_sizes, int n_in,
                              void* d_out, int out_size) {
    const float* x    = (const float*)d_in[0];
    const float* rw   = (const float*)d_in[1];
    const float* rb   = (const float*)d_in[2];
    const float* e0_k = (const float*)d_in[3];
    const float* e0_g = (const float*)d_in[4];
    const float* e0_b = (const float*)d_in[5];
    const float* e0_m = (const float*)d_in[6];
    const float* e0_v = (const float*)d_in[7];
    const float* e0_pw= (const float*)d_in[8];
    const float* e0_pb= (const float*)d_in[9];
    const float* e1_k = (const float*)d_in[10];
    const float* e1_g = (const float*)d_in[11];
    const float* e1_b = (const float*)d_in[12];
    const float* e1_m = (const float*)d_in[13];
    const float* e1_v = (const float*)d_in[14];
    const float* e1_pw= (const float*)d_in[15];
    const float* e1_pb= (const float*)d_in[16];
    const float* e2_k = (const float*)d_in[17];
    const float* e2_g = (const float*)d_in[18];
    const float* e2_b = (const float*)d_in[19];
    const float* e2_m = (const float*)d_in[20];
    const float* e2_v = (const float*)d_in[21];
    const float* e2_pw= (const float*)d_in[22];
    const float* e2_pb= (const float*)d_in[23];
    float* out = (float*)d_out;

    cudaStream_t s1 = g_str[0];
    cudaStream_t s2 = g_str[1];
    cudaEvent_t evFork = g_ev[0];
    cudaEvent_t eD0    = g_ev[1];
    cudaEvent_t eF0    = g_ev[2];
    cudaEvent_t eF1    = g_ev[3];
    cudaEvent_t eO0    = g_ev[4];

    pool_prep_kernel<<<NB*NC + 1024, 256>>>(x, e0_pw, e1_pw, e2_pw, e2_k);
    route_kernel<<<1, 32>>>(rw, rb);

    cudaEventRecord(evFork, 0);
    cudaStreamWaitEvent(s1, evFork, 0);

    dim3 hgrid(NHW/128, NC/128, NB/2);   // (32, 2, 16)
    dim3 dgrid(NC, NB/2);                // (256, 16)

    // s1: feat halves
    feat_gemm_kernel<<<hgrid, 256, 0, s1>>>(0, e2_g, e2_b, e2_m, e2_v);
    cudaEventRecord(eF0, s1);
    feat_gemm_kernel<<<hgrid, 256, 0, s1>>>(NB/2, e2_g, e2_b, e2_m, e2_v);
    cudaEventRecord(eF1, s1);

    // s0 (default): dwconv halves
    dwconv_bn_gelu_kernel<<<dgrid, 256>>>(0,
        x, e0_k, e0_g, e0_b, e0_m, e0_v,
           e1_k, e1_g, e1_b, e1_m, e1_v);
    cudaEventRecord(eD0, 0);
    dwconv_bn_gelu_kernel<<<dgrid, 256>>>(NB/2,
        x, e0_k, e0_g, e0_b, e0_m, e0_v,
           e1_k, e1_g, e1_b, e1_m, e1_v);

    // s2: out(h0) as soon as h0 features are ready (overlaps h1 feature work)
    cudaStreamWaitEvent(s2, eD0, 0);
    cudaStreamWaitEvent(s2, eF0, 0);
    out_gemm_kernel<<<hgrid, 256, 0, s2>>>(0, e0_pb, e1_pb, e2_pb, out);
    cudaEventRecord(eO0, s2);

    // s0: out(h1) after dwconv(h1) (program order) + feat(h1)
    cudaStreamWaitEvent(0, eF1, 0);
    out_gemm_kernel<<<hgrid, 256>>>(NB/2, e0_pb, e1_pb, e2_pb, out);

    // join side work back to origin stream
    cudaStreamWaitEvent(0, eO0, 0);
}